// round 11
// baseline (speedup 1.0000x reference)
#include <cuda_runtime.h>
#include <math.h>

#define NN    512
#define BIT   64
#define NCLS  100
#define ALPHA 5.0f
#define LAM   1.0f
#define NB    NN                // 512 blocks, one anchor row each
#define NT    256               // threads per block

// Scratch (allocation-free: __device__ globals)
__device__ float4 g_part[NB];    // {rowloss_or_0, valid, l2partial, 0} per block
__device__ unsigned int g_done = 0;

// ---------------------------------------------------------------------------
// Single fused kernel, one anchor row per block. R11: fully parallel rank-
// based positive compaction (no serial thread-0 section) and an inverted pair
// loop (thread owns its two n's; ~5 broadcast iterations over positives).
// ---------------------------------------------------------------------------
__global__ void __launch_bounds__(NT) fused_kernel(const float* __restrict__ u,
                                                   const float* __restrict__ y,
                                                   float* __restrict__ out) {
    __shared__ float4 s_ur[BIT / 4];               // anchor row of u      (256 B)
    __shared__ float  s_ip[NN];                    // ip row               (2 KB)
    __shared__ int    s_lbl;
    __shared__ unsigned s_gmask[16];               // pos bitmask words
    __shared__ short  s_poslist[NN];               // positive indices     (1 KB)
    __shared__ float  s_part[8];                   // per-warp pair partials
    __shared__ float  s_s2[2];                     // loss2 partials (2 warps)
    __shared__ int    s_islast;
    __shared__ float4 s_rf[NT];                    // final reduce scratch (4 KB)

    const int tid  = threadIdx.x;
    const int bid  = blockIdx.x;
    const int r    = bid;                          // anchor row
    const int lane = tid & 31;
    const int wrp  = tid >> 5;

    // --- phase 0: anchor row of u into smem + label recovery (one-hot) ---
    if (tid < BIT / 4) {                           // 16 float4 loads
        s_ur[tid] = ((const float4*)(u + (size_t)r * BIT))[tid];
    }
    if (tid < NCLS) {                              // exactly one writer
        if (y[(size_t)r * NCLS + tid] > 0.5f) s_lbl = tid;
    }
    __syncthreads();

    const int lbl = s_lbl;

    // --- scattered isneg gathers issued EARLY; hide under the dot loop ---
    const float yv1 = __ldg(y + (size_t)tid * NCLS + lbl);
    const float yv2 = __ldg(y + (size_t)(tid + NT) * NCLS + lbl);

    // --- coalesced dot phase: 16-lane segments, 16 rows per iteration ---
    {
        const float4 av = s_ur[tid & 15];
        const int seg = tid & 15;
        const int row_in_iter = tid >> 4;
        #pragma unroll 8
        for (int it = 0; it < NN / 16; ++it) {
            float4 b = ((const float4*)u)[it * (16 * BIT / 4) + tid];
            float p = av.x * b.x + av.y * b.y + av.z * b.z + av.w * b.w;
            p += __shfl_xor_sync(0xffffffffu, p, 1);
            p += __shfl_xor_sync(0xffffffffu, p, 2);
            p += __shfl_xor_sync(0xffffffffu, p, 4);
            p += __shfl_xor_sync(0xffffffffu, p, 8);
            if (seg == 0) s_ip[it * 16 + row_in_iter] = p;
        }
    }

    // --- isneg in registers (one-hot: exact 0/1); ballots from registers ---
    const bool n1 = (yv1 == 0.0f);                 // true = negative pair
    const bool n2 = (yv2 == 0.0f);
    {
        unsigned m;
        m = __ballot_sync(0xffffffffu, !n1);       // positives, j = wrp*32+lane
        if (lane == 0) s_gmask[wrp] = m;
        m = __ballot_sync(0xffffffffu, !n2);       // positives, j = 256 + ...
        if (lane == 0) s_gmask[wrp + 8] = m;
    }

    // --- loss2 partial: this block's BIT = 64 u values (from smem copy) ---
    if (tid < BIT) {
        float v  = ((const float*)s_ur)[tid];
        float sg = (v > 0.0f) ? 1.0f : ((v < 0.0f) ? -1.0f : 0.0f);
        float d  = v - sg;
        float s2 = d * d;
        #pragma unroll
        for (int o = 16; o > 0; o >>= 1) s2 += __shfl_xor_sync(0xffffffffu, s2, o);
        if (lane == 0) s_s2[wrp] = s2;
    }
    __syncthreads();

    // --- fully parallel rank-based compaction of positive indices ---
    int npos = 0;
    {
        int rank1 = 0, rank2 = 0;
        #pragma unroll
        for (int c = 0; c < 16; ++c) {
            int pc = __popc(s_gmask[c]);
            if (c < wrp)     rank1 += pc;
            if (c < wrp + 8) rank2 += pc;
            npos += pc;
        }
        unsigned lanebits = (lane == 0) ? 0u : ((1u << lane) - 1u);
        rank1 += __popc(s_gmask[wrp]     & lanebits);
        rank2 += __popc(s_gmask[wrp + 8] & lanebits);
        if (!n1) s_poslist[rank1] = (short)tid;          // positive -> own slot
        if (!n2) s_poslist[rank2] = (short)(tid + NT);
    }
    __syncthreads();

    // --- inverted pair loop: thread owns n = tid and tid+256;
    //     loop over ~npos positives with broadcast s_ip reads ---
    float acc = 0.0f;
    {
        const float ip1 = s_ip[tid];
        const float ip2 = s_ip[tid + NT];
        for (int k = 0; k < npos; ++k) {
            float ipp = s_ip[s_poslist[k]];              // broadcast LDS
            if (n1) {
                float t = ipp - ip1 - ALPHA;
                t = fminf(fmaxf(t, -100.0f), 50.0f);
                acc += __logf(1.0f + __expf(-fabsf(t))) + fmaxf(-t, 0.0f);
            }
            if (n2) {
                float t = ipp - ip2 - ALPHA;
                t = fminf(fmaxf(t, -100.0f), 50.0f);
                acc += __logf(1.0f + __expf(-fabsf(t))) + fmaxf(-t, 0.0f);
            }
        }
    }
    #pragma unroll
    for (int o = 16; o > 0; o >>= 1) acc += __shfl_xor_sync(0xffffffffu, acc, o);
    if (lane == 0) s_part[wrp] = acc;
    __syncthreads();

    // --- block epilogue: row loss + loss2 partial, publish, count arrival ---
    if (tid == 0) {
        int   np = npos;
        int   nn = NN - np;
        float rs = 0.0f;
        #pragma unroll
        for (int w2 = 0; w2 < 8; ++w2) rs += s_part[w2];
        float rl    = rs / fmaxf((float)(np * nn), 1.0f);
        float valid = (np > 0 && nn > 0) ? 1.0f : 0.0f;
        float bl2   = s_s2[0] + s_s2[1];

        g_part[bid] = make_float4(valid * rl, valid, bl2, 0.0f);
        __threadfence();
        unsigned prev = atomicAdd(&g_done, 1u);
        s_islast = (prev == NB - 1) ? 1 : 0;
    }
    __syncthreads();

    // --- last block performs the final deterministic reduction ---
    if (s_islast) {
        float4 a = __ldcg(&g_part[tid]);
        float4 b = __ldcg(&g_part[tid + NT]);
        s_rf[tid] = make_float4(a.x + b.x, a.y + b.y, a.z + b.z, 0.0f);
        __syncthreads();
        #pragma unroll
        for (int s = NT / 2; s > 0; s >>= 1) {
            if (tid < s) {
                float4 x0 = s_rf[tid];
                float4 x1 = s_rf[tid + s];
                s_rf[tid] = make_float4(x0.x + x1.x, x0.y + x1.y, x0.z + x1.z, 0.0f);
            }
            __syncthreads();
        }
        if (tid == 0) {
            float4 rres = s_rf[0];
            float count = rres.y;
            float loss1 = (count > 0.0f) ? (rres.x / fmaxf(count, 1.0f)) : 0.0f;
            float loss2 = LAM * rres.z / (float)(NN * BIT);
            out[0] = loss1 + loss2;
            g_done = 0;   // reset for next graph replay (safe: we are last)
        }
    }
}

// ---------------------------------------------------------------------------
extern "C" void kernel_launch(void* const* d_in, const int* in_sizes, int n_in,
                              void* d_out, int out_size) {
    const float* u;
    const float* y;
    if (in_sizes[0] == NN * BIT) {
        u = (const float*)d_in[0];
        y = (const float*)d_in[1];
    } else {
        u = (const float*)d_in[1];
        y = (const float*)d_in[0];
    }
    float* out = (float*)d_out;

    fused_kernel<<<NB, NT>>>(u, y, out);
}